// round 13
// baseline (speedup 1.0000x reference)
#include <cuda_runtime.h>

// ---------------------------------------------------------------------------
// 2-layer fused LSTM, persistent per-batch-tile kernel.
// B=4096, T=365, H=64 (gates=256), I=3.
// 128 CTAs x 256 threads; CTA owns 32 batch rows for the whole sequence.
// Thread (gq, bg): hidden unit j=gq (its 4 gates i,f,g,o) for 8 batches.
// Weights pre-permuted in SMEM so the 4 gates of unit j are contiguous.
// Packed fp32x2 FMA (Blackwell) doubles fp32 MAC throughput.
// ---------------------------------------------------------------------------

#define T_STEPS 365
#define HID 64
#define BT 32
#define NCTA 128
#define NTHREADS 256
#define HSTRIDE 36   // padded row stride (floats) for h buffers: 16B-aligned, low STS conflict

typedef unsigned long long ull;

#define PK2(d, x, y)    asm("mov.b64 %0, {%1, %2};" : "=l"(d) : "f"(x), "f"(y))
#define UPK2(x, y, d)   asm("mov.b64 {%0, %1}, %2;" : "=f"(x), "=f"(y) : "l"(d))
#define FMA2(acc, a, b) asm("fma.rn.f32x2 %0, %1, %2, %0;" : "+l"(acc) : "l"(a), "l"(b))

__device__ __forceinline__ float sigf(float x) {
    float e = __expf(-x);
    return __fdividef(1.0f, 1.0f + e);
}
__device__ __forceinline__ float tanhx(float x) {
    float e = __expf(2.0f * x);
    return 1.0f - __fdividef(2.0f, e + 1.0f);
}

// SMEM layout (float offsets)
#define WG0_OFF 0          // 64*256   : W_hh0 permuted, [k][j*4+p]
#define WG1_OFF 16384      // 128*256  : rows 0..63 W_ih1, 64..127 W_hh1 (permuted)
#define WI0_OFF 49152      // 3*256    : W_ih0 permuted, [i][j*4+p]
#define B0_OFF  49920      // 256
#define B1_OFF  50176      // 256
#define H1_OFF  50432      // 64*36
#define H2_OFF  52736      // 64*36
#define X_OFF   55040      // 96
#define SMEM_FLOATS 55136  // 220544 bytes

// Accumulate acc += h[k] * W[k][gates] over k=0..63.
// wG: permuted weight block [64][256]; hb: transposed h [64][HSTRIDE].
__device__ __forceinline__ void gemm64(const float* __restrict__ wG,
                                       const float* __restrict__ hb,
                                       ull* acc0, ull* acc1,
                                       int gq, int bg)
{
    const float4* wg4 = (const float4*)wG;
    const float4* hb4 = (const float4*)hb;
#pragma unroll 8
    for (int k = 0; k < 64; ++k) {
        float4 wv = wg4[k * 64 + gq];            // (w_i, w_f, w_g, w_o) of unit gq at k
        ull w01, w23;
        PK2(w01, wv.x, wv.y);
        PK2(w23, wv.z, wv.w);
        float4 ha  = hb4[k * 9 + bg * 2];        // h[k][bg*8 .. +3]  (broadcast in warp)
        float4 hbv = hb4[k * 9 + bg * 2 + 1];    // h[k][bg*8+4 .. +7]
        ull hd;
        PK2(hd, ha.x,  ha.x ); FMA2(acc0[0], hd, w01); FMA2(acc1[0], hd, w23);
        PK2(hd, ha.y,  ha.y ); FMA2(acc0[1], hd, w01); FMA2(acc1[1], hd, w23);
        PK2(hd, ha.z,  ha.z ); FMA2(acc0[2], hd, w01); FMA2(acc1[2], hd, w23);
        PK2(hd, ha.w,  ha.w ); FMA2(acc0[3], hd, w01); FMA2(acc1[3], hd, w23);
        PK2(hd, hbv.x, hbv.x); FMA2(acc0[4], hd, w01); FMA2(acc1[4], hd, w23);
        PK2(hd, hbv.y, hbv.y); FMA2(acc0[5], hd, w01); FMA2(acc1[5], hd, w23);
        PK2(hd, hbv.z, hbv.z); FMA2(acc0[6], hd, w01); FMA2(acc1[6], hd, w23);
        PK2(hd, hbv.w, hbv.w); FMA2(acc0[7], hd, w01); FMA2(acc1[7], hd, w23);
    }
}

extern "C" __global__ void __launch_bounds__(NTHREADS, 1)
lstm2_kernel(const float* __restrict__ x,
             const float* __restrict__ w_ih0, const float* __restrict__ w_hh0,
             const float* __restrict__ b_ih0, const float* __restrict__ b_hh0,
             const float* __restrict__ w_ih1, const float* __restrict__ w_hh1,
             const float* __restrict__ b_ih1, const float* __restrict__ b_hh1,
             float* __restrict__ out)
{
    extern __shared__ float sm[];
    const int tid = threadIdx.x;
    const int gq  = tid & 63;     // hidden unit j
    const int bg  = tid >> 6;     // batch octet (0..3)
    const int bBase = blockIdx.x * BT;

    float* wG0 = sm + WG0_OFF;
    float* wG1 = sm + WG1_OFF;
    float* wI0 = sm + WI0_OFF;
    float* bG0 = sm + B0_OFF;
    float* bG1 = sm + B1_OFF;
    float* h1b = sm + H1_OFF;
    float* h2b = sm + H2_OFF;
    float* xb  = sm + X_OFF;

    // ---- load + permute weights into SMEM (one-time) ----
    // dest col c -> unit j = c>>2, gate p = c&3; source gate row = p*64 + j
    for (int idx = tid; idx < 64 * 256; idx += NTHREADS) {
        int k = idx >> 8, c = idx & 255;
        int j = c >> 2, p = c & 3;
        wG0[idx] = w_hh0[(p * 64 + j) * 64 + k];
    }
    for (int idx = tid; idx < 128 * 256; idx += NTHREADS) {
        int k = idx >> 8, c = idx & 255;
        int j = c >> 2, p = c & 3;
        int g = p * 64 + j;
        wG1[idx] = (k < 64) ? w_ih1[g * 64 + k] : w_hh1[g * 64 + (k - 64)];
    }
    for (int idx = tid; idx < 3 * 256; idx += NTHREADS) {
        int i = idx >> 8, c = idx & 255;
        int j = c >> 2, p = c & 3;
        wI0[idx] = w_ih0[(p * 64 + j) * 3 + i];
    }
    {
        int c = tid;            // exactly 256 threads
        int j = c >> 2, p = c & 3;
        int g = p * 64 + j;
        bG0[c] = b_ih0[g] + b_hh0[g];
        bG1[c] = b_ih1[g] + b_hh1[g];
    }
    for (int idx = tid; idx < 64 * HSTRIDE; idx += NTHREADS) {
        h1b[idx] = 0.0f;
        h2b[idx] = 0.0f;
    }
    __syncthreads();

    // bias pairs (loop-invariant)
    ull bp01_0, bp23_0, bp01_1, bp23_1;
    {
        float4 b0v = ((const float4*)bG0)[gq];
        float4 b1v = ((const float4*)bG1)[gq];
        PK2(bp01_0, b0v.x, b0v.y); PK2(bp23_0, b0v.z, b0v.w);
        PK2(bp01_1, b1v.x, b1v.y); PK2(bp23_1, b1v.z, b1v.w);
    }

    float c1[8], c2[8];
#pragma unroll
    for (int b = 0; b < 8; ++b) { c1[b] = 0.0f; c2[b] = 0.0f; }

    // prefetch x for t=0
    float xpre = 0.0f;
    if (tid < 96)
        xpre = x[(bBase + tid / 3) * (T_STEPS * 3) + (tid % 3)];

    for (int t = 0; t < T_STEPS; ++t) {
        if (tid < 96) xb[tid] = xpre;
        __syncthreads();   // xb(t), h1b(t-1), h2b(t-1) all visible
        if (tid < 96 && t + 1 < T_STEPS)
            xpre = x[(bBase + tid / 3) * (T_STEPS * 3) + (t + 1) * 3 + (tid % 3)];

        // ---- layer 1 gates: bias + x.W_ih0^T + h1.W_hh0^T ----
        ull acc0[8], acc1[8];
#pragma unroll
        for (int b = 0; b < 8; ++b) { acc0[b] = bp01_0; acc1[b] = bp23_0; }

#pragma unroll
        for (int i = 0; i < 3; ++i) {
            float4 wv = ((const float4*)wI0)[i * 64 + gq];
            ull w01, w23; PK2(w01, wv.x, wv.y); PK2(w23, wv.z, wv.w);
#pragma unroll
            for (int b = 0; b < 8; ++b) {
                float xv = xb[(bg * 8 + b) * 3 + i];
                ull xd; PK2(xd, xv, xv);
                FMA2(acc0[b], xd, w01); FMA2(acc1[b], xd, w23);
            }
        }
        gemm64(wG0, h1b, acc0, acc1, gq, bg);
        __syncthreads();   // all reads of h1b(t-1) complete

        // ---- layer 1 cell update -> h1b(t) ----
#pragma unroll
        for (int b = 0; b < 8; ++b) {
            float pi, pf, pg, po;
            UPK2(pi, pf, acc0[b]); UPK2(pg, po, acc1[b]);
            float ig = sigf(pi), fg = sigf(pf), gg = tanhx(pg), og = sigf(po);
            float c = fg * c1[b] + ig * gg;
            c1[b] = c;
            h1b[gq * HSTRIDE + bg * 8 + b] = og * tanhx(c);
        }
        __syncthreads();   // h1b(t) ready; h2b(t-1) still intact

        // ---- layer 2 gates: bias + h1(t).W_ih1^T + h2(t-1).W_hh1^T ----
#pragma unroll
        for (int b = 0; b < 8; ++b) { acc0[b] = bp01_1; acc1[b] = bp23_1; }
        gemm64(wG1,            h1b, acc0, acc1, gq, bg);
        gemm64(wG1 + 64 * 256, h2b, acc0, acc1, gq, bg);
        __syncthreads();   // all reads of h2b(t-1) complete

        // ---- layer 2 cell update -> h2b(t) ----
#pragma unroll
        for (int b = 0; b < 8; ++b) {
            float pi, pf, pg, po;
            UPK2(pi, pf, acc0[b]); UPK2(pg, po, acc1[b]);
            float ig = sigf(pi), fg = sigf(pf), gg = tanhx(pg), og = sigf(po);
            float c = fg * c2[b] + ig * gg;
            c2[b] = c;
            float h = og * tanhx(c);
            h2b[gq * HSTRIDE + bg * 8 + b] = h;
            if (t == T_STEPS - 1)
                out[(bBase + bg * 8 + b) * HID + gq] = h;
        }
        // top-of-loop sync orders h2b(t) before next step's reads
    }
}

extern "C" void kernel_launch(void* const* d_in, const int* in_sizes, int n_in,
                              void* d_out, int out_size)
{
    const float* x     = (const float*)d_in[0];
    const float* w_ih0 = (const float*)d_in[1];
    const float* w_hh0 = (const float*)d_in[2];
    const float* b_ih0 = (const float*)d_in[3];
    const float* b_hh0 = (const float*)d_in[4];
    const float* w_ih1 = (const float*)d_in[5];
    const float* w_hh1 = (const float*)d_in[6];
    const float* b_ih1 = (const float*)d_in[7];
    const float* b_hh1 = (const float*)d_in[8];
    float* out = (float*)d_out;

    size_t smem = SMEM_FLOATS * sizeof(float);   // 220544 B
    cudaFuncSetAttribute((const void*)lstm2_kernel,
                         cudaFuncAttributeMaxDynamicSharedMemorySize, (int)smem);
    lstm2_kernel<<<NCTA, NTHREADS, smem>>>(x, w_ih0, w_hh0, b_ih0, b_hh0,
                                           w_ih1, w_hh1, b_ih1, b_hh1, out);
}